// round 3
// baseline (speedup 1.0000x reference)
#include <cuda_runtime.h>
#include <cstdint>

// out[b, c*12+i, h, w] = sum_{k,j} w1[i,k,j] * y[b,c,(h+k-4) mod 112, (w-1) mod 112, j]
//   gated by 0 <= h+k-3 < 112   (i.e. -1 <= m <= 110 where m = h+k-4)
// y[b,c,h,w,j] = sum_{j0} x[b, c*12+j0, h, w] * w2[j0, j]
//
// Fused single kernel: CTA = (h-tile of 16, c, b), full W=112.
//  - w-roll folded into stage-1 x column index (y col w <- x col (w-1) mod 112)
//  - h-roll folded into y row index (m mod 112), invalid halo rows stored as zeros
//  - all arithmetic in packed fp32x2 (fma.rn.f32x2), pairing adjacent w columns

#define HH 112
#define WW 112
#define TILE_H 16
#define YROWS 22          // TILE_H + 6 halo rows
#define NJ 12             // input channels per group
#define NI 9              // mid channels
#define NO 12             // output channels per group
#define THREADS 224

typedef unsigned long long u64;

__device__ __forceinline__ u64 fma2(u64 a, u64 b, u64 c) {
    u64 d;
    asm("fma.rn.f32x2 %0, %1, %2, %3;" : "=l"(d) : "l"(a), "l"(b), "l"(c));
    return d;
}
__device__ __forceinline__ u64 pack2(float lo, float hi) {
    u64 d;
    asm("mov.b64 %0, {%1, %2};" : "=l"(d) : "f"(lo), "f"(hi));
    return d;
}

// dynamic smem layout:
//   u64  w1d[756]   : w1 repacked to [k][j][i], each value duplicated in both f32x2 lanes
//   u64  w2d[108]   : w2 as [j0][i], duplicated
//   float ysm[YROWS][NI][WW]  (22*9*112 floats = 88704 B)
#define SMEM_W1D_ELEMS 756
#define SMEM_W2D_ELEMS 108
#define SMEM_Y_OFF ((SMEM_W1D_ELEMS + SMEM_W2D_ELEMS) * 8)
#define SMEM_TOTAL (SMEM_Y_OFF + YROWS * NI * WW * 4)

__global__ void __launch_bounds__(THREADS, 2)
fused_shiftconv_kernel(const float* __restrict__ x,
                       const float* __restrict__ w1,
                       const float* __restrict__ w2,
                       float* __restrict__ out)
{
    extern __shared__ char smem[];
    u64* w1d = reinterpret_cast<u64*>(smem);
    u64* w2d = w1d + SMEM_W1D_ELEMS;
    float* ysm = reinterpret_cast<float*>(smem + SMEM_Y_OFF);

    const int tid = threadIdx.x;
    const int h0  = blockIdx.x * TILE_H;   // 7 tiles
    const int c   = blockIdx.y;            // 2 groups
    const int b   = blockIdx.z;            // 128 batches

    // ---- weight repack (duplicated f32x2) ----
    for (int idx = tid; idx < SMEM_W1D_ELEMS; idx += THREADS) {
        // w1 input layout [i][k][j]: idx = i*63 + k*9 + j
        int i = idx / 63;
        int rem = idx - i * 63;
        int k = rem / 9;
        int j = rem - k * 9;
        float v = w1[idx];
        w1d[(k * 9 + j) * 12 + i] = pack2(v, v);
    }
    for (int idx = tid; idx < SMEM_W2D_ELEMS; idx += THREADS) {
        float v = w2[idx];            // already [j0][i]
        w2d[idx] = pack2(v, v);
    }
    __syncthreads();

    const float* xb = x + (size_t)(b * 24 + c * 12) * (HH * WW);

    // ---- stage 1: y[l][i][w] = sum_j0 x[c*12+j0, (h0+l-4) mod 112, (w-1) mod 112] * w2[j0][i]
    // invalid rows (m < -1 or m > 110) stored as zeros -> stage 2 runs gate-free.
    for (int g = tid; g < YROWS * 14; g += THREADS) {
        int l  = g / 14;             // local y row
        int wq = g - l * 14;         // 8-column group
        int m  = h0 + l - 4;
        float* ybase = ysm + (l * NI) * WW + (wq << 3);
        if (m >= -1 && m <= 110) {
            int xr = (m < 0) ? (m + HH) : m;   // only m == -1 wraps (to row 111)
            const float* xrow = xb + (size_t)xr * WW;
            u64 acc[4][NI];
            #pragma unroll
            for (int v = 0; v < 4; ++v)
                #pragma unroll
                for (int i = 0; i < NI; ++i) acc[v][i] = 0ULL;

            const int c0 = (wq << 3) - 1;      // leftmost x column (may be -1 -> wraps)
            #pragma unroll 4
            for (int j0 = 0; j0 < NJ; ++j0) {
                const float* xp = xrow + (size_t)j0 * (HH * WW);
                float xs[8];
                #pragma unroll
                for (int v = 0; v < 8; ++v) {
                    int col = c0 + v;
                    if (col < 0) col += WW;
                    xs[v] = __ldg(xp + col);
                }
                u64 xq[4];
                #pragma unroll
                for (int v = 0; v < 4; ++v) xq[v] = pack2(xs[2 * v], xs[2 * v + 1]);
                const u64* wr = w2d + j0 * NI;
                #pragma unroll
                for (int i = 0; i < NI; ++i) {
                    u64 wv = wr[i];
                    #pragma unroll
                    for (int v = 0; v < 4; ++v)
                        acc[v][i] = fma2(xq[v], wv, acc[v][i]);
                }
            }
            #pragma unroll
            for (int i = 0; i < NI; ++i)
                #pragma unroll
                for (int v = 0; v < 4; ++v)
                    *reinterpret_cast<u64*>(ybase + i * WW + 2 * v) = acc[v][i];
        } else {
            #pragma unroll
            for (int i = 0; i < NI; ++i)
                #pragma unroll
                for (int v = 0; v < 4; ++v)
                    *reinterpret_cast<u64*>(ybase + i * WW + 2 * v) = 0ULL;
        }
    }
    __syncthreads();

    // ---- stage 2: 7-tap conv over rows, 9 -> 12 channels, all in f32x2 ----
    {
        const int u  = tid % 56;          // w pair (cols 2u, 2u+1)
        const int rb = tid / 56;          // 0..3 -> 4-row block
        const int hl = rb * 4;            // local output row base
        u64 acc[4][NO];
        #pragma unroll
        for (int r = 0; r < 4; ++r)
            #pragma unroll
            for (int i = 0; i < NO; ++i) acc[r][i] = 0ULL;

        const float* ycol = ysm + 2 * u;
        #pragma unroll 1
        for (int j = 0; j < NI; ++j) {
            u64 yw[10];                   // y rows hl .. hl+9, channel j
            #pragma unroll
            for (int t = 0; t < 10; ++t)
                yw[t] = *reinterpret_cast<const u64*>(ycol + ((hl + t) * NI + j) * WW);
            #pragma unroll
            for (int k = 0; k < 7; ++k) {
                const u64* wp = w1d + (k * 9 + j) * 12;
                #pragma unroll
                for (int i = 0; i < NO; ++i) {
                    u64 wv = wp[i];
                    #pragma unroll
                    for (int r = 0; r < 4; ++r)
                        acc[r][i] = fma2(yw[r + k], wv, acc[r][i]);
                }
            }
        }

        float* ob = out + ((size_t)(b * 24 + c * 12) * HH + (h0 + hl)) * WW + 2 * u;
        #pragma unroll
        for (int i = 0; i < NO; ++i) {
            float* orow = ob + (size_t)i * (HH * WW);
            #pragma unroll
            for (int r = 0; r < 4; ++r)
                *reinterpret_cast<u64*>(orow + r * WW) = acc[r][i];
        }
    }
}

extern "C" void kernel_launch(void* const* d_in, const int* in_sizes, int n_in,
                              void* d_out, int out_size)
{
    (void)in_sizes; (void)n_in; (void)out_size;
    const float* x  = (const float*)d_in[0];
    const float* w1 = (const float*)d_in[1];
    const float* w2 = (const float*)d_in[2];
    float* out = (float*)d_out;

    cudaFuncSetAttribute(fused_shiftconv_kernel,
                         cudaFuncAttributeMaxDynamicSharedMemorySize, SMEM_TOTAL);
    dim3 grid(HH / TILE_H, 2, 128);   // (7 h-tiles, 2 groups, 128 batches)
    fused_shiftconv_kernel<<<grid, THREADS, SMEM_TOTAL>>>(x, w1, w2, out);
}

// round 4
// speedup vs baseline: 1.0789x; 1.0789x over previous
#include <cuda_runtime.h>
#include <cstdint>

// out[b, c*12+i, h, (w'+1)%112] = sum_{k,j} w1[i,k,j] * y[(h+k-4), w', j]
//   where y row m is valid iff -1 <= m <= 110 (m == -1 wraps to x row 111), else 0
// y[m, w', j] = sum_{j0} x[b, c*12+j0, m%112, w'] * w2[j0, j]
//
// w-roll folded into the OUTPUT store (so all loads are aligned/coalesced);
// h-roll + conv gating folded into stage-1 row selection / zeroing.
// All math in packed fp32x2 (fma.rn.f32x2).

#define HH 112
#define WW 112
#define TILE_H 8
#define YROWS 14          // TILE_H + 6 halo rows
#define NJ 12
#define NI 9
#define NO 12
#define THREADS 224

typedef unsigned long long u64;

__device__ __forceinline__ u64 fma2(u64 a, u64 b, u64 c) {
    u64 d;
    asm("fma.rn.f32x2 %0, %1, %2, %3;" : "=l"(d) : "l"(a), "l"(b), "l"(c));
    return d;
}
__device__ __forceinline__ u64 pack2(float lo, float hi) {
    u64 d;
    asm("mov.b64 %0, {%1, %2};" : "=l"(d) : "f"(lo), "f"(hi));
    return d;
}
__device__ __forceinline__ void unpack2(u64 v, float& lo, float& hi) {
    asm("mov.b64 {%0, %1}, %2;" : "=f"(lo), "=f"(hi) : "l"(v));
}

// dynamic smem:
//   u64  w1d[756]  : w1 repacked [k][j][i], value duplicated in both f32x2 lanes
//   u64  w2d[108]  : w2 [j0][i], duplicated
//   float ysm[YROWS][NI][WW]   (14*9*112*4 = 56448 B)
#define SMEM_W1D_ELEMS 756
#define SMEM_W2D_ELEMS 108
#define SMEM_Y_OFF ((SMEM_W1D_ELEMS + SMEM_W2D_ELEMS) * 8)
#define SMEM_TOTAL (SMEM_Y_OFF + YROWS * NI * WW * 4)

__global__ void __launch_bounds__(THREADS, 3)
fused_shiftconv_kernel(const float* __restrict__ x,
                       const float* __restrict__ w1,
                       const float* __restrict__ w2,
                       float* __restrict__ out)
{
    extern __shared__ char smem[];
    u64* w1d = reinterpret_cast<u64*>(smem);
    u64* w2d = w1d + SMEM_W1D_ELEMS;
    float* ysm = reinterpret_cast<float*>(smem + SMEM_Y_OFF);

    const int tid = threadIdx.x;
    const int h0  = blockIdx.x * TILE_H;   // 14 tiles
    const int c   = blockIdx.y;            // 2 groups
    const int b   = blockIdx.z;            // 128 batches

    // ---- weight repack (duplicated f32x2) ----
    for (int idx = tid; idx < SMEM_W1D_ELEMS; idx += THREADS) {
        // w1 input layout [i][k][j]: idx = i*63 + k*9 + j
        int i = idx / 63;
        int rem = idx - i * 63;
        int k = rem / 9;
        int j = rem - k * 9;
        float v = w1[idx];
        w1d[(k * 9 + j) * 12 + i] = pack2(v, v);
    }
    for (int idx = tid; idx < SMEM_W2D_ELEMS; idx += THREADS) {
        float v = w2[idx];
        w2d[idx] = pack2(v, v);
    }
    __syncthreads();

    const float* xb = x + (size_t)(b * 24 + c * 12) * (HH * WW);

    // ---- stage 1: y[l][i][w'] = sum_j0 x[j0, (h0+l-4)%112, w'] * w2[j0][i]
    // item = (l, wq): 4 aligned columns per item, one LDG.128 per j0.
    for (int g = tid; g < YROWS * 28; g += THREADS) {
        int l  = g / 28;
        int wq = g - l * 28;
        int m  = h0 + l - 4;
        float* ybase = ysm + (l * NI) * WW + (wq << 2);
        if (m >= -1 && m <= 110) {
            int xr = (m < 0) ? (m + HH) : m;   // only m == -1 wraps (row 111)
            const float4* xrow = reinterpret_cast<const float4*>(
                xb + (size_t)xr * WW + (wq << 2));
            u64 acc[2][NI];
            #pragma unroll
            for (int v = 0; v < 2; ++v)
                #pragma unroll
                for (int i = 0; i < NI; ++i) acc[v][i] = 0ULL;

            #pragma unroll 4
            for (int j0 = 0; j0 < NJ; ++j0) {
                float4 xv = __ldg(xrow + (size_t)j0 * (HH * WW / 4));
                u64 xq0 = pack2(xv.x, xv.y);
                u64 xq1 = pack2(xv.z, xv.w);
                const u64* wr = w2d + j0 * NI;
                #pragma unroll
                for (int i = 0; i < NI; ++i) {
                    u64 wv = wr[i];
                    acc[0][i] = fma2(xq0, wv, acc[0][i]);
                    acc[1][i] = fma2(xq1, wv, acc[1][i]);
                }
            }
            #pragma unroll
            for (int i = 0; i < NI; ++i) {
                *reinterpret_cast<u64*>(ybase + i * WW)     = acc[0][i];
                *reinterpret_cast<u64*>(ybase + i * WW + 2) = acc[1][i];
            }
        } else {
            #pragma unroll
            for (int i = 0; i < NI; ++i) {
                *reinterpret_cast<u64*>(ybase + i * WW)     = 0ULL;
                *reinterpret_cast<u64*>(ybase + i * WW + 2) = 0ULL;
            }
        }
    }
    __syncthreads();

    // ---- stage 2: 7-tap conv over rows, 9 -> 12 channels, f32x2 ----
    {
        const int u  = tid % 56;          // y w-pair (cols 2u, 2u+1)
        const int rb = tid / 56;          // 0..3
        const int hl = rb * 2;            // 2 output rows per thread
        u64 acc[2][NO];
        #pragma unroll
        for (int r = 0; r < 2; ++r)
            #pragma unroll
            for (int i = 0; i < NO; ++i) acc[r][i] = 0ULL;

        const float* ycol = ysm + 2 * u;
        #pragma unroll 1
        for (int j = 0; j < NI; ++j) {
            u64 yw[8];                    // y rows hl .. hl+7, channel j
            #pragma unroll
            for (int t = 0; t < 8; ++t)
                yw[t] = *reinterpret_cast<const u64*>(ycol + ((hl + t) * NI + j) * WW);
            #pragma unroll
            for (int k = 0; k < 7; ++k) {
                const u64* wp = w1d + (k * 9 + j) * 12;
                #pragma unroll
                for (int i = 0; i < NO; ++i) {
                    u64 wv = wp[i];
                    acc[0][i] = fma2(yw[k],     wv, acc[0][i]);
                    acc[1][i] = fma2(yw[k + 1], wv, acc[1][i]);
                }
            }
        }

        // output columns: w-roll by +1 -> out cols (2u+1) and (2u+2)%112
        const int colA = 2 * u + 1;
        const int colB = (2 * u + 2 == WW) ? 0 : 2 * u + 2;
        float* ob = out + ((size_t)(b * 24 + c * 12) * HH + (h0 + hl)) * WW;
        #pragma unroll
        for (int i = 0; i < NO; ++i) {
            float* orow = ob + (size_t)i * (HH * WW);
            #pragma unroll
            for (int r = 0; r < 2; ++r) {
                float lo, hi;
                unpack2(acc[r][i], lo, hi);
                orow[r * WW + colA] = lo;
                orow[r * WW + colB] = hi;
            }
        }
    }
}

extern "C" void kernel_launch(void* const* d_in, const int* in_sizes, int n_in,
                              void* d_out, int out_size)
{
    (void)in_sizes; (void)n_in; (void)out_size;
    const float* x  = (const float*)d_in[0];
    const float* w1 = (const float*)d_in[1];
    const float* w2 = (const float*)d_in[2];
    float* out = (float*)d_out;

    cudaFuncSetAttribute(fused_shiftconv_kernel,
                         cudaFuncAttributeMaxDynamicSharedMemorySize, SMEM_TOTAL);
    dim3 grid(HH / TILE_H, 2, 128);   // (14 h-tiles, 2 groups, 128 batches)
    fused_shiftconv_kernel<<<grid, THREADS, SMEM_TOTAL>>>(x, w1, w2, out);
}